// round 11
// baseline (speedup 1.0000x reference)
#include <cuda_runtime.h>
#include <cuda_bf16.h>
#include <math.h>
#include <stdint.h>

#define N_NODES 100000
#define N_EDGES 800000

typedef unsigned int u32;
typedef unsigned long long u64t;

// ---------------- scratch ----------------------------------------------------------
__device__ float g_A[(size_t)N_NODES * 128];     // x@W1a  (edge-gather set, L2-resident)
__device__ float g_B[(size_t)N_NODES * 128];     // x@W1b  (streamed once per node)
__device__ float g_Hagg[(size_t)N_NODES * 128];  // sum over in-edges of relu(h)
__device__ float g_dvec[128];                    // b2 @ U1b

// CSR by destination (unordered segment placement)
__device__ int    g_cnt[N_NODES];   // INVARIANT: zero on entry to kernel_launch
__device__ int    g_ctr;            // INVARIANT: zero on entry to kernel_launch
__device__ int    g_rps[N_NODES];   // segment start per node
__device__ int    g_len[N_NODES];   // segment length (= in-degree)
__device__ int    g_pos[N_NODES];
__device__ int    g_esrc[N_EDGES];
__device__ float4 g_el[N_EDGES];    // log1p(edge features), CSR order

// pre-packed mma B fragments (hi/lo bf16 pairs), layout: ((s*N + c)*4 + q)*2 + h
__device__ u32 g_Bp1hi[2 * 4096];
__device__ u32 g_Bp1lo[2 * 4096];
__device__ u32 g_Bp2hi[12288];
__device__ u32 g_Bp2lo[12288];
__device__ u32 g_Bp3hi[4096];
__device__ u32 g_Bp3lo[4096];

// ---------------- helpers ----------------------------------------------------------
__device__ __forceinline__ u32 bf16bits(float x) {
    return (u32)__bfloat16_as_ushort(__float2bfloat16_rn(x));
}
__device__ __forceinline__ float bf16val(float x) {
    return __bfloat162float(__float2bfloat16_rn(x));
}
__device__ __forceinline__ u32 pack_hi(float x, float y) {
    return bf16bits(x) | (bf16bits(y) << 16);
}
__device__ __forceinline__ u32 pack_lo(float x, float y) {
    return bf16bits(x - bf16val(x)) | (bf16bits(y - bf16val(y)) << 16);
}

__device__ __forceinline__ void mma16816(float c[4], const u32 a[4], u32 b0, u32 b1) {
    asm volatile(
        "mma.sync.aligned.m16n8k16.row.col.f32.bf16.bf16.f32 "
        "{%0,%1,%2,%3}, {%4,%5,%6,%7}, {%8,%9}, {%0,%1,%2,%3};"
        : "+f"(c[0]), "+f"(c[1]), "+f"(c[2]), "+f"(c[3])
        : "r"(a[0]), "r"(a[1]), "r"(a[2]), "r"(a[3]), "r"(b0), "r"(b1));
}

// edge message contribution: relu(a + base + sum l_i * w_i)
__device__ __forceinline__ void msg_acc(float4& acc, const float4& a, const float4& base,
                                        const float4& l, const float4& w0, const float4& w1,
                                        const float4& w2, const float4& w3) {
    acc.x += fmaxf(fmaf(l.w, w3.x, fmaf(l.z, w2.x, fmaf(l.y, w1.x, fmaf(l.x, w0.x, a.x + base.x)))), 0.f);
    acc.y += fmaxf(fmaf(l.w, w3.y, fmaf(l.z, w2.y, fmaf(l.y, w1.y, fmaf(l.x, w0.y, a.y + base.y)))), 0.f);
    acc.z += fmaxf(fmaf(l.w, w3.z, fmaf(l.z, w2.z, fmaf(l.y, w1.z, fmaf(l.x, w0.z, a.z + base.z)))), 0.f);
    acc.w += fmaxf(fmaf(l.w, w3.w, fmaf(l.z, w2.w, fmaf(l.y, w1.w, fmaf(l.x, w0.w, a.w + base.w)))), 0.f);
}

// Wcat element on the fly: rows 0..63 = U1a, rows 64..191 = V = W2 @ U1b
__device__ __forceinline__ float wcat_val(int row, int col, const float* __restrict__ U1,
                                          const float* __restrict__ W2) {
    if (row < 64) return U1[row * 128 + col];
    int i = row - 64;
    float s = 0.f;
#pragma unroll
    for (int k = 0; k < 64; k++)
        s = fmaf(W2[i * 64 + k], U1[(64 + k) * 128 + col], s);
    return s;
}

// ---------------- prep + pack (one launch) -----------------------------------------
__global__ void prep_pack_kernel(const float* __restrict__ W1, const float* __restrict__ U2,
                                 const float* __restrict__ U1, const float* __restrict__ W2,
                                 const float* __restrict__ b2) {
    int gidx = blockIdx.x * blockDim.x + threadIdx.x;  // 0 .. 24703
    if (gidx >= 24576) {
        int j = gidx - 24576;
        if (j < 128) {
            float s = 0.f;
#pragma unroll
            for (int k = 0; k < 64; k++)
                s = fmaf(b2[k], U1[(64 + k) * 128 + j], s);
            g_dvec[j] = s;
        }
        return;
    }
    int idx = gidx;
    u32 *dh, *dl;
    const float* src = nullptr;
    int N;
    bool is_wcat = false;
    if (idx < 4096)        { dh = g_Bp1hi;        dl = g_Bp1lo;        src = W1;            N = 128; }
    else if (idx < 8192)   { dh = g_Bp1hi + 4096; dl = g_Bp1lo + 4096; src = W1 + 64 * 128; N = 128; idx -= 4096; }
    else if (idx < 20480)  { dh = g_Bp2hi;        dl = g_Bp2lo;        is_wcat = true;      N = 128; idx -= 8192; }
    else                   { dh = g_Bp3hi;        dl = g_Bp3lo;        src = U2;            N = 64;  idx -= 20480; }

    int h = idx & 1;
    int rest = idx >> 1;
    int q = rest & 3;
    int rest2 = rest >> 2;
    int c = rest2 % N;
    int s = rest2 / N;
    int k0 = 16 * s + 2 * q + 8 * h;
    float f0, f1;
    if (is_wcat) {
        f0 = wcat_val(k0, c, U1, W2);
        f1 = wcat_val(k0 + 1, c, U1, W2);
    } else {
        f0 = src[(size_t)k0 * N + c];
        f1 = src[(size_t)(k0 + 1) * N + c];
    }
    dh[idx] = pack_hi(f0, f1);
    dl[idx] = pack_lo(f0, f1);
}

// ---------------- CSR build (histogram -> range alloc -> scatter) ------------------
__global__ void hist_kernel(const int* __restrict__ ei) {
    int e = blockIdx.x * blockDim.x + threadIdx.x;
    if (e < N_EDGES) atomicAdd(&g_cnt[ei[N_EDGES + e]], 1);
}

// per-node contiguous range via global counter; also restores g_cnt==0 invariant
__global__ void alloc_kernel() {
    int i = blockIdx.x * blockDim.x + threadIdx.x;
    if (i >= N_NODES) return;
    int c = g_cnt[i];
    int start = atomicAdd(&g_ctr, c);
    g_rps[i] = start;
    g_pos[i] = start;
    g_len[i] = c;
    g_cnt[i] = 0;
}

__global__ void scatter_kernel(const int* __restrict__ ei, const float* __restrict__ ef) {
    int e = blockIdx.x * blockDim.x + threadIdx.x;
    if (e >= N_EDGES) return;
    int s = ei[e];
    int d = ei[N_EDGES + e];
    int p = atomicAdd(&g_pos[d], 1);
    g_esrc[p] = s;
    float4 l;
    l.x = log1pf(ef[(size_t)e * 4 + 0]);
    l.y = log1pf(ef[(size_t)e * 4 + 1]);
    l.z = log1pf(ef[(size_t)e * 4 + 2]);
    l.w = log1pf(ef[(size_t)e * 4 + 3]);
    g_el[p] = l;
}

// ---------------- aggregation: warp per destination node, unroll 4 -----------------
__global__ __launch_bounds__(256) void agg_kernel(const float* __restrict__ W1,
                                                  const float* __restrict__ b1) {
    __shared__ float s_wc[512];
    __shared__ float s_b1[128];
    for (int t = threadIdx.x; t < 512; t += 256) s_wc[t] = W1[128 * 128 + t];
    if (threadIdx.x < 128) s_b1[threadIdx.x] = b1[threadIdx.x];
    __syncthreads();

    int warp = threadIdx.x >> 5;
    int lane = threadIdx.x & 31;
    int d = blockIdx.x * 8 + warp;   // grid = 12500 -> exactly 100000
    int s = g_rps[d];
    int e = s + g_len[d];

    float4 w0 = *(const float4*)&s_wc[0 * 128 + lane * 4];
    float4 w1 = *(const float4*)&s_wc[1 * 128 + lane * 4];
    float4 w2 = *(const float4*)&s_wc[2 * 128 + lane * 4];
    float4 w3 = *(const float4*)&s_wc[3 * 128 + lane * 4];
    float4 base = *(const float4*)(g_B + (size_t)d * 128 + lane * 4);
    float4 bb = *(const float4*)&s_b1[lane * 4];
    base.x += bb.x; base.y += bb.y; base.z += bb.z; base.w += bb.w;

    float4 acc = make_float4(0.f, 0.f, 0.f, 0.f);
    int i = s;
    for (; i + 4 <= e; i += 4) {
        int s0 = g_esrc[i], s1 = g_esrc[i + 1], s2 = g_esrc[i + 2], s3 = g_esrc[i + 3];
        float4 a0 = *(const float4*)(g_A + (size_t)s0 * 128 + lane * 4);
        float4 a1 = *(const float4*)(g_A + (size_t)s1 * 128 + lane * 4);
        float4 a2 = *(const float4*)(g_A + (size_t)s2 * 128 + lane * 4);
        float4 a3 = *(const float4*)(g_A + (size_t)s3 * 128 + lane * 4);
        float4 l0 = g_el[i], l1 = g_el[i + 1], l2 = g_el[i + 2], l3 = g_el[i + 3];
        msg_acc(acc, a0, base, l0, w0, w1, w2, w3);
        msg_acc(acc, a1, base, l1, w0, w1, w2, w3);
        msg_acc(acc, a2, base, l2, w0, w1, w2, w3);
        msg_acc(acc, a3, base, l3, w0, w1, w2, w3);
    }
    for (; i < e; i++) {
        int s0 = g_esrc[i];
        float4 a0 = *(const float4*)(g_A + (size_t)s0 * 128 + lane * 4);
        float4 l0 = g_el[i];
        msg_acc(acc, a0, base, l0, w0, w1, w2, w3);
    }
    *(float4*)(g_Hagg + (size_t)d * 128 + lane * 4) = acc;
}

// ---------------- GEMM1 (tensor core): g_A = x@W1a, g_B = x@W1b -------------------
__global__ __launch_bounds__(256) void mma_gemm1_kernel(const float* __restrict__ a_x) {
    __shared__ __align__(16) u32 sA[2][128][20];
    const int tid = threadIdx.x;
    const int lane = tid & 31;
    const int warp = tid >> 5;
    const int wm = warp >> 1, wn = warp & 1;
    const int q = lane & 3, lr = lane >> 2;
    const int row0 = blockIdx.x * 128;
    const int cb = blockIdx.y;
    const u32* __restrict__ Bhi = g_Bp1hi + cb * 4096;
    const u32* __restrict__ Blo = g_Bp1lo + cb * 4096;
    float* __restrict__ dst = cb ? g_B : g_A;

    float acc[2][8][4];
#pragma unroll
    for (int i = 0; i < 2; i++)
#pragma unroll
        for (int j = 0; j < 8; j++)
#pragma unroll
            for (int p = 0; p < 4; p++) acc[i][j][p] = 0.f;

    for (int ch = 0; ch < 2; ch++) {
        const int kc0 = ch * 32;
        __syncthreads();
#pragma unroll
        for (int it = 0; it < 4; it++) {
            int idx = tid + it * 256;
            int m = idx >> 3, fx = idx & 7;
            int gm = row0 + m;
            if (gm >= N_NODES) gm = N_NODES - 1;
            float4 v = *(const float4*)(a_x + (size_t)gm * 64 + kc0 + fx * 4);
            u32 h0 = pack_hi(v.x, v.y), h1 = pack_hi(v.z, v.w);
            u32 l0 = pack_lo(v.x, v.y), l1 = pack_lo(v.z, v.w);
            *(u64t*)&sA[0][m][fx * 2] = ((u64t)h1 << 32) | h0;
            *(u64t*)&sA[1][m][fx * 2] = ((u64t)l1 << 32) | l0;
        }
        __syncthreads();
#pragma unroll
        for (int s = 0; s < 2; s++) {
            const int sg = ch * 2 + s;
            u32 ah[2][4], al[2][4];
#pragma unroll
            for (int i = 0; i < 2; i++) {
                int rr = wm * 32 + i * 16 + lr;
                ah[i][0] = sA[0][rr][8 * s + q];
                ah[i][1] = sA[0][rr + 8][8 * s + q];
                ah[i][2] = sA[0][rr][8 * s + q + 4];
                ah[i][3] = sA[0][rr + 8][8 * s + q + 4];
                al[i][0] = sA[1][rr][8 * s + q];
                al[i][1] = sA[1][rr + 8][8 * s + q];
                al[i][2] = sA[1][rr][8 * s + q + 4];
                al[i][3] = sA[1][rr + 8][8 * s + q + 4];
            }
#pragma unroll
            for (int j = 0; j < 8; j++) {
                int c = wn * 64 + j * 8 + lr;
                int bidx = ((sg * 128 + c) * 4 + q) * 2;
                u64t bh = *(const u64t*)(Bhi + bidx);
                u64t bl = *(const u64t*)(Blo + bidx);
                u32 bh0 = (u32)bh, bh1 = (u32)(bh >> 32);
                u32 bl0 = (u32)bl, bl1 = (u32)(bl >> 32);
#pragma unroll
                for (int i = 0; i < 2; i++) {
                    mma16816(acc[i][j], ah[i], bh0, bh1);
                    mma16816(acc[i][j], al[i], bh0, bh1);
                    mma16816(acc[i][j], ah[i], bl0, bl1);
                }
            }
        }
    }
    const int rbase = row0 + wm * 32 + lr;
#pragma unroll
    for (int i = 0; i < 2; i++) {
        int r0 = rbase + i * 16, r1 = r0 + 8;
#pragma unroll
        for (int j = 0; j < 8; j++) {
            int n = wn * 64 + j * 8 + 2 * q;
            if (r0 < N_NODES)
                *(float2*)(dst + (size_t)r0 * 128 + n) = make_float2(acc[i][j][0], acc[i][j][1]);
            if (r1 < N_NODES)
                *(float2*)(dst + (size_t)r1 * 128 + n) = make_float2(acc[i][j][2], acc[i][j][3]);
        }
    }
}

// ---------------- fused update: out = relu([x|Hagg]@Wcat + deg*dvec + bu1)@U2 + bu2
#define SA_(h, m, w) sraw[((h)*128 + (m)) * 20 + (w)]
#define SG_(h, m, w) sraw[((h)*128 + (m)) * 68 + (w)]

__global__ __launch_bounds__(256) void fused_upd_kernel(const float* __restrict__ a_x,
                                                        const float* __restrict__ bu1,
                                                        const float* __restrict__ bu2,
                                                        float* __restrict__ outp) {
    extern __shared__ __align__(16) u32 sraw[];   // 2*128*68 u32 = 69632 B
    const int tid = threadIdx.x;
    const int lane = tid & 31;
    const int warp = tid >> 5;
    const int wm = warp >> 1, wn = warp & 1;
    const int q = lane & 3, lr = lane >> 2;
    const int row0 = blockIdx.x * 128;

    if (blockIdx.x == 0 && tid == 0) g_ctr = 0;   // restore invariant for next call

    float acc[2][8][4];
#pragma unroll
    for (int i = 0; i < 2; i++)
#pragma unroll
        for (int j = 0; j < 8; j++)
#pragma unroll
            for (int p = 0; p < 4; p++) acc[i][j][p] = 0.f;

    // ---- stage 1: [x|Hagg] @ Wcat (K=192) ----
    for (int ch = 0; ch < 6; ch++) {
        const int kc0 = ch * 32;
        const float* srcp;
        int ld, koff;
        if (kc0 < 64) { srcp = a_x;                  ld = 64;  koff = kc0; }
        else          { srcp = (const float*)g_Hagg; ld = 128; koff = kc0 - 64; }
        __syncthreads();
#pragma unroll
        for (int it = 0; it < 4; it++) {
            int idx = tid + it * 256;
            int m = idx >> 3, fx = idx & 7;
            int gm = row0 + m;
            if (gm >= N_NODES) gm = N_NODES - 1;
            float4 v = *(const float4*)(srcp + (size_t)gm * ld + koff + fx * 4);
            u32 h0 = pack_hi(v.x, v.y), h1 = pack_hi(v.z, v.w);
            u32 l0 = pack_lo(v.x, v.y), l1 = pack_lo(v.z, v.w);
            *(u64t*)&SA_(0, m, fx * 2) = ((u64t)h1 << 32) | h0;
            *(u64t*)&SA_(1, m, fx * 2) = ((u64t)l1 << 32) | l0;
        }
        __syncthreads();
#pragma unroll
        for (int s = 0; s < 2; s++) {
            const int sg = ch * 2 + s;
            u32 ah[2][4], al[2][4];
#pragma unroll
            for (int i = 0; i < 2; i++) {
                int rr = wm * 32 + i * 16 + lr;
                ah[i][0] = SA_(0, rr, 8 * s + q);
                ah[i][1] = SA_(0, rr + 8, 8 * s + q);
                ah[i][2] = SA_(0, rr, 8 * s + q + 4);
                ah[i][3] = SA_(0, rr + 8, 8 * s + q + 4);
                al[i][0] = SA_(1, rr, 8 * s + q);
                al[i][1] = SA_(1, rr + 8, 8 * s + q);
                al[i][2] = SA_(1, rr, 8 * s + q + 4);
                al[i][3] = SA_(1, rr + 8, 8 * s + q + 4);
            }
#pragma unroll
            for (int j = 0; j < 8; j++) {
                int c = wn * 64 + j * 8 + lr;
                int bidx = ((sg * 128 + c) * 4 + q) * 2;
                u64t bh = *(const u64t*)(g_Bp2hi + bidx);
                u64t bl = *(const u64t*)(g_Bp2lo + bidx);
                u32 bh0 = (u32)bh, bh1 = (u32)(bh >> 32);
                u32 bl0 = (u32)bl, bl1 = (u32)(bl >> 32);
#pragma unroll
                for (int i = 0; i < 2; i++) {
                    mma16816(acc[i][j], ah[i], bh0, bh1);
                    mma16816(acc[i][j], al[i], bh0, bh1);
                    mma16816(acc[i][j], ah[i], bl0, bl1);
                }
            }
        }
    }

    // ---- epilogue 1: relu(acc + deg*dvec + bu1) -> sG (bf16 hi/lo) ----
    __syncthreads();   // all SA reads done before aliasing as SG
#pragma unroll
    for (int i = 0; i < 2; i++) {
        int rl0 = wm * 32 + i * 16 + lr;
        int rl1 = rl0 + 8;
        int gr0 = row0 + rl0;
        int gr1 = row0 + rl1;
        if (gr0 >= N_NODES) gr0 = N_NODES - 1;
        if (gr1 >= N_NODES) gr1 = N_NODES - 1;
        float dg0 = (float)g_len[gr0];
        float dg1 = (float)g_len[gr1];
#pragma unroll
        for (int j = 0; j < 8; j++) {
            int n = wn * 64 + j * 8 + 2 * q;
            float dv0 = g_dvec[n], dv1 = g_dvec[n + 1];
            float u0 = bu1[n], u1 = bu1[n + 1];
            float o0 = fmaxf(acc[i][j][0] + fmaf(dg0, dv0, u0), 0.f);
            float o1 = fmaxf(acc[i][j][1] + fmaf(dg0, dv1, u1), 0.f);
            float o2 = fmaxf(acc[i][j][2] + fmaf(dg1, dv0, u0), 0.f);
            float o3 = fmaxf(acc[i][j][3] + fmaf(dg1, dv1, u1), 0.f);
            int w = wn * 32 + j * 4 + q;
            SG_(0, rl0, w) = pack_hi(o0, o1);
            SG_(1, rl0, w) = pack_lo(o0, o1);
            SG_(0, rl1, w) = pack_hi(o2, o3);
            SG_(1, rl1, w) = pack_lo(o2, o3);
        }
    }
    __syncthreads();

    // ---- stage 2: G @ U2 (K=128, N=64) ----
    float acc2[2][4][4];
#pragma unroll
    for (int i = 0; i < 2; i++)
#pragma unroll
        for (int j = 0; j < 4; j++)
#pragma unroll
            for (int p = 0; p < 4; p++) acc2[i][j][p] = 0.f;

#pragma unroll
    for (int s2 = 0; s2 < 8; s2++) {
        u32 ah[2][4], al[2][4];
#pragma unroll
        for (int i = 0; i < 2; i++) {
            int rr = wm * 32 + i * 16 + lr;
            ah[i][0] = SG_(0, rr, 8 * s2 + q);
            ah[i][1] = SG_(0, rr + 8, 8 * s2 + q);
            ah[i][2] = SG_(0, rr, 8 * s2 + q + 4);
            ah[i][3] = SG_(0, rr + 8, 8 * s2 + q + 4);
            al[i][0] = SG_(1, rr, 8 * s2 + q);
            al[i][1] = SG_(1, rr + 8, 8 * s2 + q);
            al[i][2] = SG_(1, rr, 8 * s2 + q + 4);
            al[i][3] = SG_(1, rr + 8, 8 * s2 + q + 4);
        }
#pragma unroll
        for (int j = 0; j < 4; j++) {
            int c = wn * 32 + j * 8 + lr;
            int bidx = ((s2 * 64 + c) * 4 + q) * 2;
            u64t bh = *(const u64t*)(g_Bp3hi + bidx);
            u64t bl = *(const u64t*)(g_Bp3lo + bidx);
            u32 bh0 = (u32)bh, bh1 = (u32)(bh >> 32);
            u32 bl0 = (u32)bl, bl1 = (u32)(bl >> 32);
#pragma unroll
            for (int i = 0; i < 2; i++) {
                mma16816(acc2[i][j], ah[i], bh0, bh1);
                mma16816(acc2[i][j], al[i], bh0, bh1);
                mma16816(acc2[i][j], ah[i], bl0, bl1);
            }
        }
    }

    // ---- epilogue 2: + bu2 -> out ----
    const int rbase = row0 + wm * 32 + lr;
#pragma unroll
    for (int i = 0; i < 2; i++) {
        int r0 = rbase + i * 16, r1 = r0 + 8;
#pragma unroll
        for (int j = 0; j < 4; j++) {
            int n = wn * 32 + j * 8 + 2 * q;
            float u0 = bu2[n], u1 = bu2[n + 1];
            if (r0 < N_NODES)
                *(float2*)(outp + (size_t)r0 * 64 + n) =
                    make_float2(acc2[i][j][0] + u0, acc2[i][j][1] + u1);
            if (r1 < N_NODES)
                *(float2*)(outp + (size_t)r1 * 64 + n) =
                    make_float2(acc2[i][j][2] + u0, acc2[i][j][3] + u1);
        }
    }
}

// ---------------- launch ----------------------------------------------------------
extern "C" void kernel_launch(void* const* d_in, const int* in_sizes, int n_in,
                              void* d_out, int out_size) {
    const float* x   = (const float*)d_in[0];
    const int*   ei  = (const int*)d_in[1];
    const float* ef  = (const float*)d_in[2];
    const float* W1  = (const float*)d_in[3];
    const float* b1  = (const float*)d_in[4];
    const float* W2  = (const float*)d_in[5];
    const float* b2  = (const float*)d_in[6];
    const float* U1  = (const float*)d_in[7];
    const float* bu1 = (const float*)d_in[8];
    const float* U2  = (const float*)d_in[9];
    const float* bu2 = (const float*)d_in[10];
    float* out = (float*)d_out;

    cudaFuncSetAttribute(fused_upd_kernel, cudaFuncAttributeMaxDynamicSharedMemorySize, 69632);

    prep_pack_kernel<<<97, 256>>>(W1, U2, U1, W2, b2);
    mma_gemm1_kernel<<<dim3(782, 2), 256>>>(x);
    hist_kernel<<<782, 1024>>>(ei);
    alloc_kernel<<<98, 1024>>>();
    scatter_kernel<<<782, 1024>>>(ei, ef);
    agg_kernel<<<12500, 256>>>(W1, b1);
    fused_upd_kernel<<<782, 256, 69632>>>(x, bu1, bu2, out);
}

// round 12
// speedup vs baseline: 1.0024x; 1.0024x over previous
#include <cuda_runtime.h>
#include <cuda_bf16.h>
#include <math.h>
#include <stdint.h>

#define N_NODES 100000
#define N_EDGES 800000

typedef unsigned int u32;
typedef unsigned long long u64t;

// ---------------- scratch ----------------------------------------------------------
__device__ float g_A[(size_t)N_NODES * 128];     // x@W1a  (edge-gather set, L2-resident)
__device__ float g_B[(size_t)N_NODES * 128];     // x@W1b  (streamed once per node)
__device__ float g_Hagg[(size_t)N_NODES * 128];  // sum over in-edges of relu(h)
__device__ float g_dvec[128];                    // b2 @ U1b

// CSR by destination (unordered segment placement)
__device__ int    g_cnt[N_NODES];   // INVARIANT: zero on entry to kernel_launch
__device__ int    g_ctr;            // INVARIANT: zero on entry to kernel_launch
__device__ int    g_rps[N_NODES];   // segment start per node
__device__ int    g_len[N_NODES];   // segment length (= in-degree)
__device__ int    g_pos[N_NODES];
__device__ int    g_esrc[N_EDGES];
__device__ float4 g_el[N_EDGES];    // log1p(edge features), CSR order

// pre-packed mma B fragments (hi/lo bf16 pairs), layout: ((s*N + c)*4 + q)*2 + h
__device__ u32 g_Bp1hi[2 * 4096];
__device__ u32 g_Bp1lo[2 * 4096];
__device__ u32 g_Bp2hi[12288];
__device__ u32 g_Bp2lo[12288];
__device__ u32 g_Bp3hi[4096];
__device__ u32 g_Bp3lo[4096];

// ---------------- helpers ----------------------------------------------------------
__device__ __forceinline__ u32 bf16bits(float x) {
    return (u32)__bfloat16_as_ushort(__float2bfloat16_rn(x));
}
__device__ __forceinline__ float bf16val(float x) {
    return __bfloat162float(__float2bfloat16_rn(x));
}
__device__ __forceinline__ u32 pack_hi(float x, float y) {
    return bf16bits(x) | (bf16bits(y) << 16);
}
__device__ __forceinline__ u32 pack_lo(float x, float y) {
    return bf16bits(x - bf16val(x)) | (bf16bits(y - bf16val(y)) << 16);
}

__device__ __forceinline__ void mma16816(float c[4], const u32 a[4], u32 b0, u32 b1) {
    asm volatile(
        "mma.sync.aligned.m16n8k16.row.col.f32.bf16.bf16.f32 "
        "{%0,%1,%2,%3}, {%4,%5,%6,%7}, {%8,%9}, {%0,%1,%2,%3};"
        : "+f"(c[0]), "+f"(c[1]), "+f"(c[2]), "+f"(c[3])
        : "r"(a[0]), "r"(a[1]), "r"(a[2]), "r"(a[3]), "r"(b0), "r"(b1));
}

// edge message contribution: relu(a + base + sum l_i * w_i)
__device__ __forceinline__ void msg_acc(float4& acc, const float4& a, const float4& base,
                                        const float4& l, const float4& w0, const float4& w1,
                                        const float4& w2, const float4& w3) {
    acc.x += fmaxf(fmaf(l.w, w3.x, fmaf(l.z, w2.x, fmaf(l.y, w1.x, fmaf(l.x, w0.x, a.x + base.x)))), 0.f);
    acc.y += fmaxf(fmaf(l.w, w3.y, fmaf(l.z, w2.y, fmaf(l.y, w1.y, fmaf(l.x, w0.y, a.y + base.y)))), 0.f);
    acc.z += fmaxf(fmaf(l.w, w3.z, fmaf(l.z, w2.z, fmaf(l.y, w1.z, fmaf(l.x, w0.z, a.z + base.z)))), 0.f);
    acc.w += fmaxf(fmaf(l.w, w3.w, fmaf(l.z, w2.w, fmaf(l.y, w1.w, fmaf(l.x, w0.w, a.w + base.w)))), 0.f);
}

// Wcat element on the fly: rows 0..63 = U1a, rows 64..191 = V = W2 @ U1b
__device__ __forceinline__ float wcat_val(int row, int col, const float* __restrict__ U1,
                                          const float* __restrict__ W2) {
    if (row < 64) return U1[row * 128 + col];
    int i = row - 64;
    float s = 0.f;
#pragma unroll
    for (int k = 0; k < 64; k++)
        s = fmaf(W2[i * 64 + k], U1[(64 + k) * 128 + col], s);
    return s;
}

// ---------------- prep + pack (one launch) -----------------------------------------
__global__ void prep_pack_kernel(const float* __restrict__ W1, const float* __restrict__ U2,
                                 const float* __restrict__ U1, const float* __restrict__ W2,
                                 const float* __restrict__ b2) {
    int gidx = blockIdx.x * blockDim.x + threadIdx.x;  // 0 .. 24703
    if (gidx >= 24576) {
        int j = gidx - 24576;
        if (j < 128) {
            float s = 0.f;
#pragma unroll
            for (int k = 0; k < 64; k++)
                s = fmaf(b2[k], U1[(64 + k) * 128 + j], s);
            g_dvec[j] = s;
        }
        return;
    }
    int idx = gidx;
    u32 *dh, *dl;
    const float* src = nullptr;
    int N;
    bool is_wcat = false;
    if (idx < 4096)        { dh = g_Bp1hi;        dl = g_Bp1lo;        src = W1;            N = 128; }
    else if (idx < 8192)   { dh = g_Bp1hi + 4096; dl = g_Bp1lo + 4096; src = W1 + 64 * 128; N = 128; idx -= 4096; }
    else if (idx < 20480)  { dh = g_Bp2hi;        dl = g_Bp2lo;        is_wcat = true;      N = 128; idx -= 8192; }
    else                   { dh = g_Bp3hi;        dl = g_Bp3lo;        src = U2;            N = 64;  idx -= 20480; }

    int h = idx & 1;
    int rest = idx >> 1;
    int q = rest & 3;
    int rest2 = rest >> 2;
    int c = rest2 % N;
    int s = rest2 / N;
    int k0 = 16 * s + 2 * q + 8 * h;
    float f0, f1;
    if (is_wcat) {
        f0 = wcat_val(k0, c, U1, W2);
        f1 = wcat_val(k0 + 1, c, U1, W2);
    } else {
        f0 = src[(size_t)k0 * N + c];
        f1 = src[(size_t)(k0 + 1) * N + c];
    }
    dh[idx] = pack_hi(f0, f1);
    dl[idx] = pack_lo(f0, f1);
}

// ---------------- CSR build (histogram -> range alloc -> scatter) ------------------
__global__ void hist_kernel(const int* __restrict__ ei) {
    int e = blockIdx.x * blockDim.x + threadIdx.x;
    if (e < N_EDGES) atomicAdd(&g_cnt[ei[N_EDGES + e]], 1);
}

// per-node contiguous range via global counter; also restores g_cnt==0 invariant
__global__ void alloc_kernel() {
    int i = blockIdx.x * blockDim.x + threadIdx.x;
    if (i >= N_NODES) return;
    int c = g_cnt[i];
    int start = atomicAdd(&g_ctr, c);
    g_rps[i] = start;
    g_pos[i] = start;
    g_len[i] = c;
    g_cnt[i] = 0;
}

__global__ void scatter_kernel(const int* __restrict__ ei, const float* __restrict__ ef) {
    int e = blockIdx.x * blockDim.x + threadIdx.x;
    if (e >= N_EDGES) return;
    int s = ei[e];
    int d = ei[N_EDGES + e];
    int p = atomicAdd(&g_pos[d], 1);
    g_esrc[p] = s;
    float4 l;
    l.x = log1pf(ef[(size_t)e * 4 + 0]);
    l.y = log1pf(ef[(size_t)e * 4 + 1]);
    l.z = log1pf(ef[(size_t)e * 4 + 2]);
    l.w = log1pf(ef[(size_t)e * 4 + 3]);
    g_el[p] = l;
}

// ---------------- aggregation: warp per destination node, unroll 4 -----------------
__global__ __launch_bounds__(256) void agg_kernel(const float* __restrict__ W1,
                                                  const float* __restrict__ b1) {
    __shared__ float s_wc[512];
    __shared__ float s_b1[128];
    for (int t = threadIdx.x; t < 512; t += 256) s_wc[t] = W1[128 * 128 + t];
    if (threadIdx.x < 128) s_b1[threadIdx.x] = b1[threadIdx.x];
    __syncthreads();

    int warp = threadIdx.x >> 5;
    int lane = threadIdx.x & 31;
    int d = blockIdx.x * 8 + warp;   // grid = 12500 -> exactly 100000
    int s = g_rps[d];
    int e = s + g_len[d];

    float4 w0 = *(const float4*)&s_wc[0 * 128 + lane * 4];
    float4 w1 = *(const float4*)&s_wc[1 * 128 + lane * 4];
    float4 w2 = *(const float4*)&s_wc[2 * 128 + lane * 4];
    float4 w3 = *(const float4*)&s_wc[3 * 128 + lane * 4];
    float4 base = *(const float4*)(g_B + (size_t)d * 128 + lane * 4);
    float4 bb = *(const float4*)&s_b1[lane * 4];
    base.x += bb.x; base.y += bb.y; base.z += bb.z; base.w += bb.w;

    float4 acc = make_float4(0.f, 0.f, 0.f, 0.f);
    int i = s;
    for (; i + 4 <= e; i += 4) {
        int s0 = g_esrc[i], s1 = g_esrc[i + 1], s2 = g_esrc[i + 2], s3 = g_esrc[i + 3];
        float4 a0 = *(const float4*)(g_A + (size_t)s0 * 128 + lane * 4);
        float4 a1 = *(const float4*)(g_A + (size_t)s1 * 128 + lane * 4);
        float4 a2 = *(const float4*)(g_A + (size_t)s2 * 128 + lane * 4);
        float4 a3 = *(const float4*)(g_A + (size_t)s3 * 128 + lane * 4);
        float4 l0 = g_el[i], l1 = g_el[i + 1], l2 = g_el[i + 2], l3 = g_el[i + 3];
        msg_acc(acc, a0, base, l0, w0, w1, w2, w3);
        msg_acc(acc, a1, base, l1, w0, w1, w2, w3);
        msg_acc(acc, a2, base, l2, w0, w1, w2, w3);
        msg_acc(acc, a3, base, l3, w0, w1, w2, w3);
    }
    for (; i < e; i++) {
        int s0 = g_esrc[i];
        float4 a0 = *(const float4*)(g_A + (size_t)s0 * 128 + lane * 4);
        float4 l0 = g_el[i];
        msg_acc(acc, a0, base, l0, w0, w1, w2, w3);
    }
    *(float4*)(g_Hagg + (size_t)d * 128 + lane * 4) = acc;
}

// ---------------- GEMM1 (tensor core): g_A = x@W1a, g_B = x@W1b -------------------
__global__ __launch_bounds__(256) void mma_gemm1_kernel(const float* __restrict__ a_x) {
    __shared__ __align__(16) u32 sA[2][128][20];
    const int tid = threadIdx.x;
    const int lane = tid & 31;
    const int warp = tid >> 5;
    const int wm = warp >> 1, wn = warp & 1;
    const int q = lane & 3, lr = lane >> 2;
    const int row0 = blockIdx.x * 128;
    const int cb = blockIdx.y;
    const u32* __restrict__ Bhi = g_Bp1hi + cb * 4096;
    const u32* __restrict__ Blo = g_Bp1lo + cb * 4096;
    float* __restrict__ dst = cb ? g_B : g_A;

    float acc[2][8][4];
#pragma unroll
    for (int i = 0; i < 2; i++)
#pragma unroll
        for (int j = 0; j < 8; j++)
#pragma unroll
            for (int p = 0; p < 4; p++) acc[i][j][p] = 0.f;

    for (int ch = 0; ch < 2; ch++) {
        const int kc0 = ch * 32;
        __syncthreads();
#pragma unroll
        for (int it = 0; it < 4; it++) {
            int idx = tid + it * 256;
            int m = idx >> 3, fx = idx & 7;
            int gm = row0 + m;
            if (gm >= N_NODES) gm = N_NODES - 1;
            float4 v = *(const float4*)(a_x + (size_t)gm * 64 + kc0 + fx * 4);
            u32 h0 = pack_hi(v.x, v.y), h1 = pack_hi(v.z, v.w);
            u32 l0 = pack_lo(v.x, v.y), l1 = pack_lo(v.z, v.w);
            *(u64t*)&sA[0][m][fx * 2] = ((u64t)h1 << 32) | h0;
            *(u64t*)&sA[1][m][fx * 2] = ((u64t)l1 << 32) | l0;
        }
        __syncthreads();
#pragma unroll
        for (int s = 0; s < 2; s++) {
            const int sg = ch * 2 + s;
            u32 ah[2][4], al[2][4];
#pragma unroll
            for (int i = 0; i < 2; i++) {
                int rr = wm * 32 + i * 16 + lr;
                ah[i][0] = sA[0][rr][8 * s + q];
                ah[i][1] = sA[0][rr + 8][8 * s + q];
                ah[i][2] = sA[0][rr][8 * s + q + 4];
                ah[i][3] = sA[0][rr + 8][8 * s + q + 4];
                al[i][0] = sA[1][rr][8 * s + q];
                al[i][1] = sA[1][rr + 8][8 * s + q];
                al[i][2] = sA[1][rr][8 * s + q + 4];
                al[i][3] = sA[1][rr + 8][8 * s + q + 4];
            }
#pragma unroll
            for (int j = 0; j < 8; j++) {
                int c = wn * 64 + j * 8 + lr;
                int bidx = ((sg * 128 + c) * 4 + q) * 2;
                u64t bh = *(const u64t*)(Bhi + bidx);
                u64t bl = *(const u64t*)(Blo + bidx);
                u32 bh0 = (u32)bh, bh1 = (u32)(bh >> 32);
                u32 bl0 = (u32)bl, bl1 = (u32)(bl >> 32);
#pragma unroll
                for (int i = 0; i < 2; i++) {
                    mma16816(acc[i][j], ah[i], bh0, bh1);
                    mma16816(acc[i][j], al[i], bh0, bh1);
                    mma16816(acc[i][j], ah[i], bl0, bl1);
                }
            }
        }
    }
    const int rbase = row0 + wm * 32 + lr;
#pragma unroll
    for (int i = 0; i < 2; i++) {
        int r0 = rbase + i * 16, r1 = r0 + 8;
#pragma unroll
        for (int j = 0; j < 8; j++) {
            int n = wn * 64 + j * 8 + 2 * q;
            if (r0 < N_NODES)
                *(float2*)(dst + (size_t)r0 * 128 + n) = make_float2(acc[i][j][0], acc[i][j][1]);
            if (r1 < N_NODES)
                *(float2*)(dst + (size_t)r1 * 128 + n) = make_float2(acc[i][j][2], acc[i][j][3]);
        }
    }
}

// ---------------- fused update: out = relu([x|Hagg]@Wcat + deg*dvec + bu1)@U2 + bu2
#define SA_(h, m, w) sraw[((h)*128 + (m)) * 20 + (w)]
#define SG_(h, m, w) sraw[((h)*128 + (m)) * 68 + (w)]

__global__ __launch_bounds__(256) void fused_upd_kernel(const float* __restrict__ a_x,
                                                        const float* __restrict__ bu1,
                                                        const float* __restrict__ bu2,
                                                        float* __restrict__ outp) {
    extern __shared__ __align__(16) u32 sraw[];   // 2*128*68 u32 = 69632 B
    const int tid = threadIdx.x;
    const int lane = tid & 31;
    const int warp = tid >> 5;
    const int wm = warp >> 1, wn = warp & 1;
    const int q = lane & 3, lr = lane >> 2;
    const int row0 = blockIdx.x * 128;

    if (blockIdx.x == 0 && tid == 0) g_ctr = 0;   // restore invariant for next call

    float acc[2][8][4];
#pragma unroll
    for (int i = 0; i < 2; i++)
#pragma unroll
        for (int j = 0; j < 8; j++)
#pragma unroll
            for (int p = 0; p < 4; p++) acc[i][j][p] = 0.f;

    // ---- stage 1: [x|Hagg] @ Wcat (K=192) ----
    for (int ch = 0; ch < 6; ch++) {
        const int kc0 = ch * 32;
        const float* srcp;
        int ld, koff;
        if (kc0 < 64) { srcp = a_x;                  ld = 64;  koff = kc0; }
        else          { srcp = (const float*)g_Hagg; ld = 128; koff = kc0 - 64; }
        __syncthreads();
#pragma unroll
        for (int it = 0; it < 4; it++) {
            int idx = tid + it * 256;
            int m = idx >> 3, fx = idx & 7;
            int gm = row0 + m;
            if (gm >= N_NODES) gm = N_NODES - 1;
            float4 v = *(const float4*)(srcp + (size_t)gm * ld + koff + fx * 4);
            u32 h0 = pack_hi(v.x, v.y), h1 = pack_hi(v.z, v.w);
            u32 l0 = pack_lo(v.x, v.y), l1 = pack_lo(v.z, v.w);
            *(u64t*)&SA_(0, m, fx * 2) = ((u64t)h1 << 32) | h0;
            *(u64t*)&SA_(1, m, fx * 2) = ((u64t)l1 << 32) | l0;
        }
        __syncthreads();
#pragma unroll
        for (int s = 0; s < 2; s++) {
            const int sg = ch * 2 + s;
            u32 ah[2][4], al[2][4];
#pragma unroll
            for (int i = 0; i < 2; i++) {
                int rr = wm * 32 + i * 16 + lr;
                ah[i][0] = SA_(0, rr, 8 * s + q);
                ah[i][1] = SA_(0, rr + 8, 8 * s + q);
                ah[i][2] = SA_(0, rr, 8 * s + q + 4);
                ah[i][3] = SA_(0, rr + 8, 8 * s + q + 4);
                al[i][0] = SA_(1, rr, 8 * s + q);
                al[i][1] = SA_(1, rr + 8, 8 * s + q);
                al[i][2] = SA_(1, rr, 8 * s + q + 4);
                al[i][3] = SA_(1, rr + 8, 8 * s + q + 4);
            }
#pragma unroll
            for (int j = 0; j < 8; j++) {
                int c = wn * 64 + j * 8 + lr;
                int bidx = ((sg * 128 + c) * 4 + q) * 2;
                u64t bh = *(const u64t*)(g_Bp2hi + bidx);
                u64t bl = *(const u64t*)(g_Bp2lo + bidx);
                u32 bh0 = (u32)bh, bh1 = (u32)(bh >> 32);
                u32 bl0 = (u32)bl, bl1 = (u32)(bl >> 32);
#pragma unroll
                for (int i = 0; i < 2; i++) {
                    mma16816(acc[i][j], ah[i], bh0, bh1);
                    mma16816(acc[i][j], al[i], bh0, bh1);
                    mma16816(acc[i][j], ah[i], bl0, bl1);
                }
            }
        }
    }

    // ---- epilogue 1: relu(acc + deg*dvec + bu1) -> sG (bf16 hi/lo) ----
    __syncthreads();   // all SA reads done before aliasing as SG
#pragma unroll
    for (int i = 0; i < 2; i++) {
        int rl0 = wm * 32 + i * 16 + lr;
        int rl1 = rl0 + 8;
        int gr0 = row0 + rl0;
        int gr1 = row0 + rl1;
        if (gr0 >= N_NODES) gr0 = N_NODES - 1;
        if (gr1 >= N_NODES) gr1 = N_NODES - 1;
        float dg0 = (float)g_len[gr0];
        float dg1 = (float)g_len[gr1];
#pragma unroll
        for (int j = 0; j < 8; j++) {
            int n = wn * 64 + j * 8 + 2 * q;
            float dv0 = g_dvec[n], dv1 = g_dvec[n + 1];
            float u0 = bu1[n], u1 = bu1[n + 1];
            float o0 = fmaxf(acc[i][j][0] + fmaf(dg0, dv0, u0), 0.f);
            float o1 = fmaxf(acc[i][j][1] + fmaf(dg0, dv1, u1), 0.f);
            float o2 = fmaxf(acc[i][j][2] + fmaf(dg1, dv0, u0), 0.f);
            float o3 = fmaxf(acc[i][j][3] + fmaf(dg1, dv1, u1), 0.f);
            int w = wn * 32 + j * 4 + q;
            SG_(0, rl0, w) = pack_hi(o0, o1);
            SG_(1, rl0, w) = pack_lo(o0, o1);
            SG_(0, rl1, w) = pack_hi(o2, o3);
            SG_(1, rl1, w) = pack_lo(o2, o3);
        }
    }
    __syncthreads();

    // ---- stage 2: G @ U2 (K=128, N=64) ----
    float acc2[2][4][4];
#pragma unroll
    for (int i = 0; i < 2; i++)
#pragma unroll
        for (int j = 0; j < 4; j++)
#pragma unroll
            for (int p = 0; p < 4; p++) acc2[i][j][p] = 0.f;

#pragma unroll
    for (int s2 = 0; s2 < 8; s2++) {
        u32 ah[2][4], al[2][4];
#pragma unroll
        for (int i = 0; i < 2; i++) {
            int rr = wm * 32 + i * 16 + lr;
            ah[i][0] = SG_(0, rr, 8 * s2 + q);
            ah[i][1] = SG_(0, rr + 8, 8 * s2 + q);
            ah[i][2] = SG_(0, rr, 8 * s2 + q + 4);
            ah[i][3] = SG_(0, rr + 8, 8 * s2 + q + 4);
            al[i][0] = SG_(1, rr, 8 * s2 + q);
            al[i][1] = SG_(1, rr + 8, 8 * s2 + q);
            al[i][2] = SG_(1, rr, 8 * s2 + q + 4);
            al[i][3] = SG_(1, rr + 8, 8 * s2 + q + 4);
        }
#pragma unroll
        for (int j = 0; j < 4; j++) {
            int c = wn * 32 + j * 8 + lr;
            int bidx = ((s2 * 64 + c) * 4 + q) * 2;
            u64t bh = *(const u64t*)(g_Bp3hi + bidx);
            u64t bl = *(const u64t*)(g_Bp3lo + bidx);
            u32 bh0 = (u32)bh, bh1 = (u32)(bh >> 32);
            u32 bl0 = (u32)bl, bl1 = (u32)(bl >> 32);
#pragma unroll
            for (int i = 0; i < 2; i++) {
                mma16816(acc2[i][j], ah[i], bh0, bh1);
                mma16816(acc2[i][j], al[i], bh0, bh1);
                mma16816(acc2[i][j], ah[i], bl0, bl1);
            }
        }
    }

    // ---- epilogue 2: + bu2 -> out ----
    const int rbase = row0 + wm * 32 + lr;
#pragma unroll
    for (int i = 0; i < 2; i++) {
        int r0 = rbase + i * 16, r1 = r0 + 8;
#pragma unroll
        for (int j = 0; j < 4; j++) {
            int n = wn * 32 + j * 8 + 2 * q;
            float u0 = bu2[n], u1 = bu2[n + 1];
            if (r0 < N_NODES)
                *(float2*)(outp + (size_t)r0 * 64 + n) =
                    make_float2(acc2[i][j][0] + u0, acc2[i][j][1] + u1);
            if (r1 < N_NODES)
                *(float2*)(outp + (size_t)r1 * 64 + n) =
                    make_float2(acc2[i][j][2] + u0, acc2[i][j][3] + u1);
        }
    }
}

// ---------------- launch ----------------------------------------------------------
extern "C" void kernel_launch(void* const* d_in, const int* in_sizes, int n_in,
                              void* d_out, int out_size) {
    const float* x   = (const float*)d_in[0];
    const int*   ei  = (const int*)d_in[1];
    const float* ef  = (const float*)d_in[2];
    const float* W1  = (const float*)d_in[3];
    const float* b1  = (const float*)d_in[4];
    const float* W2  = (const float*)d_in[5];
    const float* b2  = (const float*)d_in[6];
    const float* U1  = (const float*)d_in[7];
    const float* bu1 = (const float*)d_in[8];
    const float* U2  = (const float*)d_in[9];
    const float* bu2 = (const float*)d_in[10];
    float* out = (float*)d_out;

    cudaFuncSetAttribute(fused_upd_kernel, cudaFuncAttributeMaxDynamicSharedMemorySize, 69632);

    prep_pack_kernel<<<97, 256>>>(W1, U2, U1, W2, b2);
    mma_gemm1_kernel<<<dim3(782, 2), 256>>>(x);
    hist_kernel<<<782, 1024>>>(ei);
    alloc_kernel<<<98, 1024>>>();
    scatter_kernel<<<782, 1024>>>(ei, ef);
    agg_kernel<<<12500, 256>>>(W1, b1);
    fused_upd_kernel<<<782, 256, 69632>>>(x, bu1, bu2, out);
}